// round 1
// baseline (speedup 1.0000x reference)
#include <cuda_runtime.h>

// NeuS volume-rendering weights, telescoped closed form.
//
// Key identity: with sig = sigmoid(sdf * s),
//   1 - alpha[i] = sig[i+1]/sig[i]   (unclipped alpha, used by cumprod)
//   trans[i]     = sig[i]/sig[0]     (telescoping product), trans[0] := 0
//   weight[i]    = max(0, sig[i]-sig[i+1]) / sig[0]   for 1 <= i <= S-2
//   weight[0] = weight[S-1] = 0
//
// Outputs (concatenated in reference return order into d_out):
//   pixel    [R,3]   at offset 0
//   invdepth [R]     at offset R*3
//   weight   [R,S]   at offset R*4

#define N_RAYS    65536
#define N_SAMPLES 128

__global__ void __launch_bounds__(256, 8)
neus_render_kernel(const float* __restrict__ sdf,
                   const float* __restrict__ color,
                   const float* __restrict__ z_vals,
                   const float* __restrict__ s_ptr,
                   const float* __restrict__ bg_color,
                   float* __restrict__ out)
{
    const unsigned ray  = (blockIdx.x * blockDim.x + threadIdx.x) >> 5;
    const unsigned lane = threadIdx.x & 31u;
    if (ray >= N_RAYS) return;

    const float s = s_ptr[0];

    // ---- load 4 sdf samples (coalesced float4) ----
    const float4 sd =
        reinterpret_cast<const float4*>(sdf + (size_t)ray * N_SAMPLES)[lane];

    // sigmoid(x*s) = 1/(1+exp(-x*s))
    float sg0 = __frcp_rn(1.0f + __expf(-sd.x * s));
    float sg1 = __frcp_rn(1.0f + __expf(-sd.y * s));
    float sg2 = __frcp_rn(1.0f + __expf(-sd.z * s));
    float sg3 = __frcp_rn(1.0f + __expf(-sd.w * s));

    // neighbor: sig of sample 4*lane+4 = next lane's sg0 (lane 31: unused)
    const float nxt  = __shfl_down_sync(0xffffffffu, sg0, 1);
    // sig[0] of the ray, broadcast from lane 0
    const float sig0 = __shfl_sync(0xffffffffu, sg0, 0);
    const float inv0 = 1.0f / sig0;

    float w0 = fmaxf(sg0 - sg1, 0.0f) * inv0;
    float w1 = fmaxf(sg1 - sg2, 0.0f) * inv0;
    float w2 = fmaxf(sg2 - sg3, 0.0f) * inv0;
    float w3 = (lane == 31u) ? 0.0f : fmaxf(sg3 - nxt, 0.0f) * inv0;
    if (lane == 0u) w0 = 0.0f;   // trans[0] = 0 -> weight[0] = 0

    // ---- store weights [R,S] ----
    float* out_weight = out + (size_t)N_RAYS * 4;
    float4 wv = make_float4(w0, w1, w2, w3);
    reinterpret_cast<float4*>(out_weight + (size_t)ray * N_SAMPLES)[lane] = wv;

    // ---- invdepth accumulation ----
    const float4 z =
        reinterpret_cast<const float4*>(z_vals + (size_t)ray * N_SAMPLES)[lane];
    float invd = w0 / z.x + w1 / z.y + w2 / z.z + w3 / z.w;

    // ---- color accumulation: [S,3] interleaved; lane covers floats 12L..12L+11 ----
    const float4* cp =
        reinterpret_cast<const float4*>(color + (size_t)ray * N_SAMPLES * 3) + lane * 3;
    const float4 c0 = cp[0];
    const float4 c1 = cp[1];
    const float4 c2 = cp[2];
    // sample k of this lane -> rgb at floats {3k,3k+1,3k+2} within (c0,c1,c2)
    float r = w0 * c0.x + w1 * c0.w + w2 * c1.z + w3 * c2.y;
    float g = w0 * c0.y + w1 * c1.x + w2 * c1.w + w3 * c2.z;
    float b = w0 * c0.z + w1 * c1.y + w2 * c2.x + w3 * c2.w;
    float wsum = w0 + w1 + w2 + w3;

    // ---- warp butterfly reduction of 5 values ----
    #pragma unroll
    for (int off = 16; off > 0; off >>= 1) {
        r    += __shfl_xor_sync(0xffffffffu, r,    off);
        g    += __shfl_xor_sync(0xffffffffu, g,    off);
        b    += __shfl_xor_sync(0xffffffffu, b,    off);
        invd += __shfl_xor_sync(0xffffffffu, invd, off);
        wsum += __shfl_xor_sync(0xffffffffu, wsum, off);
    }

    if (lane == 0u) {
        const float resid = 1.0f - wsum;
        float* out_pixel = out;
        float* out_invd  = out + (size_t)N_RAYS * 3;
        out_pixel[ray * 3 + 0] = r + resid * bg_color[0];
        out_pixel[ray * 3 + 1] = g + resid * bg_color[1];
        out_pixel[ray * 3 + 2] = b + resid * bg_color[2];
        out_invd[ray] = invd;
    }
}

extern "C" void kernel_launch(void* const* d_in, const int* in_sizes, int n_in,
                              void* d_out, int out_size)
{
    const float* sdf      = (const float*)d_in[0];
    const float* color    = (const float*)d_in[1];
    const float* z_vals   = (const float*)d_in[2];
    const float* s        = (const float*)d_in[3];
    const float* bg_color = (const float*)d_in[4];
    float* out = (float*)d_out;

    // 1 warp per ray, 8 rays per 256-thread block
    const int blocks = N_RAYS / 8;
    neus_render_kernel<<<blocks, 256>>>(sdf, color, z_vals, s, bg_color, out);
}

// round 3
// speedup vs baseline: 1.0204x; 1.0204x over previous
#include <cuda_runtime.h>

// NeuS volume-rendering weights, telescoped closed form.
//
//   sig = sigmoid(sdf * s)
//   1 - alpha[i] = sig[i+1]/sig[i]  (unclipped, used by cumprod)
//   trans[i]     = sig[i]/sig[0]    (telescopes), trans[0] := 0
//   weight[i]    = max(0, sig[i]-sig[i+1]) / sig[0]  for 1 <= i <= S-2
//   weight[0] = weight[S-1] = 0
//
// Outputs concatenated into d_out:
//   pixel [R,3] @0, invdepth [R] @R*3, weight [R,S] @R*4

#define N_RAYS    65536
#define N_SAMPLES 128

__device__ __forceinline__ float4 ldcs4(const float4* p) {
    return __ldcs(p);
}

__global__ void __launch_bounds__(256, 8)
neus_render_kernel(const float* __restrict__ sdf,
                   const float* __restrict__ color,
                   const float* __restrict__ z_vals,
                   const float* __restrict__ s_ptr,
                   const float* __restrict__ bg_color,
                   float* __restrict__ out)
{
    const unsigned ray  = (blockIdx.x * blockDim.x + threadIdx.x) >> 5;
    const unsigned lane = threadIdx.x & 31u;
    if (ray >= N_RAYS) return;

    // ---- front-batch ALL global loads (max MLP, streaming hint) ----
    const float4 sd = ldcs4(reinterpret_cast<const float4*>(
                            sdf + (size_t)ray * N_SAMPLES) + lane);
    const float4 z  = ldcs4(reinterpret_cast<const float4*>(
                            z_vals + (size_t)ray * N_SAMPLES) + lane);
    const float4* cp = reinterpret_cast<const float4*>(
                            color + (size_t)ray * N_SAMPLES * 3) + lane * 3;
    const float4 c0 = ldcs4(cp + 0);
    const float4 c1 = ldcs4(cp + 1);
    const float4 c2 = ldcs4(cp + 2);

    const float s = s_ptr[0];

    // sigmoid via fast exp + fast division (MUFU only, no Newton fixup)
    const float sg0 = __fdividef(1.0f, 1.0f + __expf(-sd.x * s));
    const float sg1 = __fdividef(1.0f, 1.0f + __expf(-sd.y * s));
    const float sg2 = __fdividef(1.0f, 1.0f + __expf(-sd.z * s));
    const float sg3 = __fdividef(1.0f, 1.0f + __expf(-sd.w * s));

    // neighbor sig (next lane's sg0); sig[0] broadcast from lane 0
    const float nxt  = __shfl_down_sync(0xffffffffu, sg0, 1);
    const float sig0 = __shfl_sync(0xffffffffu, sg0, 0);
    const float inv0 = __fdividef(1.0f, sig0);

    float w0 = fmaxf(sg0 - sg1, 0.0f) * inv0;
    float w1 = fmaxf(sg1 - sg2, 0.0f) * inv0;
    float w2 = fmaxf(sg2 - sg3, 0.0f) * inv0;
    float w3 = (lane == 31u) ? 0.0f : fmaxf(sg3 - nxt, 0.0f) * inv0;
    if (lane == 0u) w0 = 0.0f;   // trans[0] = 0

    // ---- streaming store of weights [R,S] ----
    float* out_weight = out + (size_t)N_RAYS * 4;
    __stcs(reinterpret_cast<float4*>(out_weight + (size_t)ray * N_SAMPLES) + lane,
           make_float4(w0, w1, w2, w3));

    // ---- invdepth: w * rcp(z), fast path ----
    float invd = w0 * __fdividef(1.0f, z.x)
               + w1 * __fdividef(1.0f, z.y)
               + w2 * __fdividef(1.0f, z.z)
               + w3 * __fdividef(1.0f, z.w);

    // ---- color accumulation ([S,3] interleaved in c0..c2) ----
    float r = w0 * c0.x + w1 * c0.w + w2 * c1.z + w3 * c2.y;
    float g = w0 * c0.y + w1 * c1.x + w2 * c1.w + w3 * c2.z;
    float b = w0 * c0.z + w1 * c1.y + w2 * c2.x + w3 * c2.w;
    float wsum = w0 + w1 + w2 + w3;

    // ---- warp butterfly reduction of 5 values ----
    #pragma unroll
    for (int off = 16; off > 0; off >>= 1) {
        r    += __shfl_xor_sync(0xffffffffu, r,    off);
        g    += __shfl_xor_sync(0xffffffffu, g,    off);
        b    += __shfl_xor_sync(0xffffffffu, b,    off);
        invd += __shfl_xor_sync(0xffffffffu, invd, off);
        wsum += __shfl_xor_sync(0xffffffffu, wsum, off);
    }

    if (lane == 0u) {
        const float resid = 1.0f - wsum;
        out[ray * 3 + 0] = r + resid * bg_color[0];
        out[ray * 3 + 1] = g + resid * bg_color[1];
        out[ray * 3 + 2] = b + resid * bg_color[2];
        out[(size_t)N_RAYS * 3 + ray] = invd;
    }
}

extern "C" void kernel_launch(void* const* d_in, const int* in_sizes, int n_in,
                              void* d_out, int out_size)
{
    const float* sdf      = (const float*)d_in[0];
    const float* color    = (const float*)d_in[1];
    const float* z_vals   = (const float*)d_in[2];
    const float* s        = (const float*)d_in[3];
    const float* bg_color = (const float*)d_in[4];
    float* out = (float*)d_out;

    neus_render_kernel<<<N_RAYS / 8, 256>>>(sdf, color, z_vals, s, bg_color, out);
}

// round 7
// speedup vs baseline: 1.1452x; 1.1223x over previous
#include <cuda_runtime.h>

// NeuS volume-rendering weights, telescoped closed form.
//
//   sig = sigmoid(sdf * s)
//   1 - alpha[i] = sig[i+1]/sig[i]  (unclipped, used by cumprod)
//   trans[i]     = sig[i]/sig[0]    (telescopes), trans[0] := 0
//   weight[i]    = max(0, sig[i]-sig[i+1]) / sig[0],  1 <= i <= S-2
//   weight[0] = weight[S-1] = 0
//
// Background fold: pixel = sum w*(c - bg) + bg   (removes wsum reduction)
//
// Outputs concatenated into d_out:
//   pixel [R,3] @0, invdepth [R] @R*3, weight [R,S] @R*4

#define N_RAYS    65536
#define N_SAMPLES 128
#define WARPS_PER_BLOCK 8

__global__ void __launch_bounds__(256)
neus_render_kernel(const float* __restrict__ sdf,
                   const float* __restrict__ color,
                   const float* __restrict__ z_vals,
                   const float* __restrict__ s_ptr,
                   const float* __restrict__ bg_color,
                   float* __restrict__ out)
{
    // per-warp color staging: 96 float4 = one ray's [128,3] row
    __shared__ float4 cbuf[WARPS_PER_BLOCK * 96];

    const unsigned ray  = (blockIdx.x * blockDim.x + threadIdx.x) >> 5;
    const unsigned lane = threadIdx.x & 31u;
    const unsigned wid  = threadIdx.x >> 5;
    if (ray >= N_RAYS) return;

    // ---- front-batch all 5 global loads (color coalesced: 4 lines/LDG) ----
    const float4* cg = reinterpret_cast<const float4*>(
                           color + (size_t)ray * N_SAMPLES * 3);
    const float4 t0 = cg[lane];
    const float4 t1 = cg[lane + 32];
    const float4 t2 = cg[lane + 64];
    const float4 sd = reinterpret_cast<const float4*>(
                          sdf + (size_t)ray * N_SAMPLES)[lane];
    const float4 z  = reinterpret_cast<const float4*>(
                          z_vals + (size_t)ray * N_SAMPLES)[lane];

    // stage color through smem to get per-sample layout without strided LDG
    float4* wb = cbuf + wid * 96;
    wb[lane]      = t0;
    wb[lane + 32] = t1;
    wb[lane + 64] = t2;

    const float s   = s_ptr[0];
    const float bgr = bg_color[0];
    const float bgg = bg_color[1];
    const float bgb = bg_color[2];

    // sigmoid via MUFU exp + fast division
    const float sg0 = __fdividef(1.0f, 1.0f + __expf(-sd.x * s));
    const float sg1 = __fdividef(1.0f, 1.0f + __expf(-sd.y * s));
    const float sg2 = __fdividef(1.0f, 1.0f + __expf(-sd.z * s));
    const float sg3 = __fdividef(1.0f, 1.0f + __expf(-sd.w * s));

    const float nxt  = __shfl_down_sync(0xffffffffu, sg0, 1);
    const float sig0 = __shfl_sync(0xffffffffu, sg0, 0);
    const float inv0 = __fdividef(1.0f, sig0);

    float w0 = fmaxf(sg0 - sg1, 0.0f) * inv0;
    float w1 = fmaxf(sg1 - sg2, 0.0f) * inv0;
    float w2 = fmaxf(sg2 - sg3, 0.0f) * inv0;
    float w3 = (lane == 31u) ? 0.0f : fmaxf(sg3 - nxt, 0.0f) * inv0;
    if (lane == 0u) w0 = 0.0f;   // trans[0] = 0

    // ---- streaming store of weights [R,S] ----
    float* out_weight = out + (size_t)N_RAYS * 4;
    __stcs(reinterpret_cast<float4*>(out_weight + (size_t)ray * N_SAMPLES) + lane,
           make_float4(w0, w1, w2, w3));

    // ---- invdepth ----
    float invd = w0 * __fdividef(1.0f, z.x)
               + w1 * __fdividef(1.0f, z.y)
               + w2 * __fdividef(1.0f, z.z)
               + w3 * __fdividef(1.0f, z.w);

    // ---- read back this lane's 4 samples of color (conflict-free LDS.128) ----
    __syncwarp();
    const float4 c0 = wb[lane * 3 + 0];
    const float4 c1 = wb[lane * 3 + 1];
    const float4 c2 = wb[lane * 3 + 2];

    // accumulate w*(c - bg); bg added back once on lane 0
    float r = w0 * (c0.x - bgr) + w1 * (c0.w - bgr)
            + w2 * (c1.z - bgr) + w3 * (c2.y - bgr);
    float g = w0 * (c0.y - bgg) + w1 * (c1.x - bgg)
            + w2 * (c1.w - bgg) + w3 * (c2.z - bgg);
    float b = w0 * (c0.z - bgb) + w1 * (c1.y - bgb)
            + w2 * (c2.x - bgb) + w3 * (c2.w - bgb);

    // ---- warp butterfly reduction of 4 values ----
    #pragma unroll
    for (int off = 16; off > 0; off >>= 1) {
        r    += __shfl_xor_sync(0xffffffffu, r,    off);
        g    += __shfl_xor_sync(0xffffffffu, g,    off);
        b    += __shfl_xor_sync(0xffffffffu, b,    off);
        invd += __shfl_xor_sync(0xffffffffu, invd, off);
    }

    if (lane == 0u) {
        out[ray * 3 + 0] = r + bgr;
        out[ray * 3 + 1] = g + bgg;
        out[ray * 3 + 2] = b + bgb;
        out[(size_t)N_RAYS * 3 + ray] = invd;
    }
}

extern "C" void kernel_launch(void* const* d_in, const int* in_sizes, int n_in,
                              void* d_out, int out_size)
{
    const float* sdf      = (const float*)d_in[0];
    const float* color    = (const float*)d_in[1];
    const float* z_vals   = (const float*)d_in[2];
    const float* s        = (const float*)d_in[3];
    const float* bg_color = (const float*)d_in[4];
    float* out = (float*)d_out;

    neus_render_kernel<<<N_RAYS / 8, 256>>>(sdf, color, z_vals, s, bg_color, out);
}